// round 6
// baseline (speedup 1.0000x reference)
#include <cuda_runtime.h>
#include <cstdint>

// ComplexBlockLinear, mma.sync tf32, Karatsuba 3-mult complex GEMM,
// cp.async double-buffered. CTA = 64 rows x 1 block (128 cols), 16 warps
// (2 M x 8 N), warp tile 32x16 -> 48 acc regs (fits 512thr @ <=128 regs).
// t1=xr@wr, t2=xi@wi, t3=(xr+xi)@(wr+wi); re=t1-t2, im=t3-t1-t2.

#define NBLK 8
#define BS 128
#define HD 1024
#define CTA_M 64
#define KC 16
#define NCHUNK (BS / KC)     // 8
#define THREADS 512

// smem floats per stage: XR 64x20, XI 64x20, WW 16x264
#define XSTR 20
#define WSTR 264
#define XR_OFF 0
#define XI_OFF 5120
#define WW_OFF 10240
#define STAGE_BYTES 27136
#define SMEM_TOTAL (2 * STAGE_BYTES)   // 54272

__device__ __forceinline__ unsigned f2tf(float x) {
    unsigned u;
    asm("cvt.rna.tf32.f32 %0, %1;" : "=r"(u) : "f"(x));
    return u;
}
__device__ __forceinline__ uint32_t smem_u32(const void* p) {
    uint32_t a;
    asm("{ .reg .u64 t; cvta.to.shared.u64 t, %1; cvt.u32.u64 %0, t; }"
        : "=r"(a) : "l"(p));
    return a;
}
__device__ __forceinline__ void cp16(uint32_t dst, const void* src) {
    asm volatile("cp.async.ca.shared.global [%0], [%1], 16;"
                 :: "r"(dst), "l"(src) : "memory");
}
__device__ __forceinline__ void cp_commit() {
    asm volatile("cp.async.commit_group;" ::: "memory");
}
template <int N>
__device__ __forceinline__ void cp_wait() {
    asm volatile("cp.async.wait_group %0;" :: "n"(N) : "memory");
}
__device__ __forceinline__ void mma_tf32(float* d, const unsigned* a,
                                         unsigned b0, unsigned b1) {
    asm volatile(
        "mma.sync.aligned.m16n8k8.row.col.f32.tf32.tf32.f32 "
        "{%0,%1,%2,%3},{%4,%5,%6,%7},{%8,%9},{%0,%1,%2,%3};\n"
        : "+f"(d[0]), "+f"(d[1]), "+f"(d[2]), "+f"(d[3])
        : "r"(a[0]), "r"(a[1]), "r"(a[2]), "r"(a[3]), "r"(b0), "r"(b1));
}

__global__ __launch_bounds__(THREADS)
void cbl_kar16_kernel(const float* __restrict__ xre,
                      const float* __restrict__ xim,
                      const float* __restrict__ w,
                      float* __restrict__ out) {
    extern __shared__ char smem[];
    const uint32_t sb = smem_u32(smem);

    const int tid  = threadIdx.x;
    const int lane = tid & 31;
    const int warp = tid >> 5;
    const int wm   = warp >> 3;    // 0..1  -> rows wm*32..+32
    const int wn   = warp & 7;     // 0..7  -> cols wn*16..+16

    const int row0 = blockIdx.x * CTA_M;
    const int nb   = blockIdx.y;

    // X staging: 64 rows x 16 k = 256 chunks per array; tid<256 -> xr, else xi
    const int xi_sel = tid >> 8;                // 0 or 1
    const int xidx   = tid & 255;
    const int xs_r   = xidx >> 2;               // 0..63
    const float* x_src0 = (xi_sel ? xim : xre) +
        (size_t)(row0 + xs_r) * HD + nb * BS + (xidx & 3) * 4;
    const uint32_t x_dst_off =
        (xi_sel ? XI_OFF : XR_OFF) + xs_r * (XSTR * 4) + (xidx & 3) * 16;

    float t1[2][2][4], t2[2][2][4], t3[2][2][4];
#pragma unroll
    for (int a = 0; a < 2; a++)
#pragma unroll
        for (int b = 0; b < 2; b++)
#pragma unroll
            for (int c = 0; c < 4; c++) {
                t1[a][b][c] = 0.f; t2[a][b][c] = 0.f; t3[a][b][c] = 0.f;
            }

    auto issue = [&](int c) {
        const uint32_t base = sb + (c & 1) * STAGE_BYTES;
        const int k0 = c * KC;
        cp16(base + x_dst_off, x_src0 + k0);
        // W: 16 k-rows x 64 chunks (16B = 2 complex) = 1024 chunks, 2/thread
#pragma unroll
        for (int q = 0; q < 2; ++q) {
            const int e  = q * THREADS + tid;   // 0..1023
            const int kk = e >> 6;              // 0..15
            const int oc = e & 63;              // 0..63
            const float* src = w +
                ((size_t)((nb * BS + k0 + kk) * BS) + oc * 2) * 2;
            cp16(base + WW_OFF + kk * (WSTR * 4) + oc * 16, src);
        }
        cp_commit();
    };

    issue(0);

#pragma unroll 1
    for (int c = 0; c < NCHUNK; ++c) {
        if (c + 1 < NCHUNK) { issue(c + 1); cp_wait<1>(); }
        else                { cp_wait<0>(); }
        __syncthreads();

        const float* sXR = (const float*)(smem + (c & 1) * STAGE_BYTES + XR_OFF);
        const float* sXI = (const float*)(smem + (c & 1) * STAGE_BYTES + XI_OFF);
        const float* sWW = (const float*)(smem + (c & 1) * STAGE_BYTES + WW_OFF);

#pragma unroll
        for (int ks = 0; ks < KC / 8; ++ks) {
            const int kk = ks * 8;
            unsigned ar[2][4], ai[2][4], as_[2][4];
#pragma unroll
            for (int mt = 0; mt < 2; ++mt) {
                const int rr = wm * 32 + mt * 16 + (lane >> 2);
                const int cc = kk + (lane & 3);
                float fr[4], fi[4];
                fr[0] = sXR[rr * XSTR + cc];
                fr[1] = sXR[(rr + 8) * XSTR + cc];
                fr[2] = sXR[rr * XSTR + cc + 4];
                fr[3] = sXR[(rr + 8) * XSTR + cc + 4];
                fi[0] = sXI[rr * XSTR + cc];
                fi[1] = sXI[(rr + 8) * XSTR + cc];
                fi[2] = sXI[rr * XSTR + cc + 4];
                fi[3] = sXI[(rr + 8) * XSTR + cc + 4];
#pragma unroll
                for (int j = 0; j < 4; ++j) {
                    ar[mt][j]  = f2tf(fr[j]);
                    ai[mt][j]  = f2tf(fi[j]);
                    as_[mt][j] = f2tf(fr[j] + fi[j]);
                }
            }
#pragma unroll
            for (int nt = 0; nt < 2; ++nt) {
                const int n  = wn * 16 + nt * 8 + (lane >> 2);
                const int kb = kk + (lane & 3);
                const float2 p0 = *(const float2*)&sWW[kb * WSTR + n * 2];
                const float2 p1 = *(const float2*)&sWW[(kb + 4) * WSTR + n * 2];
                const unsigned br0 = f2tf(p0.x);
                const unsigned bi0 = f2tf(p0.y);
                const unsigned bs0 = f2tf(p0.x + p0.y);
                const unsigned br1 = f2tf(p1.x);
                const unsigned bi1 = f2tf(p1.y);
                const unsigned bs1 = f2tf(p1.x + p1.y);
#pragma unroll
                for (int mt = 0; mt < 2; ++mt) {
                    mma_tf32(t1[mt][nt], ar[mt],  br0, br1);
                    mma_tf32(t2[mt][nt], ai[mt],  bi0, bi1);
                    mma_tf32(t3[mt][nt], as_[mt], bs0, bs1);
                }
            }
        }
        __syncthreads();
    }

    // epilogue: re = t1 - t2; im = t3 - t1 - t2; interleaved float4 stores
#pragma unroll
    for (int mt = 0; mt < 2; ++mt) {
        const int r_lo = row0 + wm * 32 + mt * 16 + (lane >> 2);
#pragma unroll
        for (int nt = 0; nt < 2; ++nt) {
            const int col = nb * BS + wn * 16 + nt * 8 + (lane & 3) * 2;
            float re0 = t1[mt][nt][0] - t2[mt][nt][0];
            float im0 = t3[mt][nt][0] - t1[mt][nt][0] - t2[mt][nt][0];
            float re1 = t1[mt][nt][1] - t2[mt][nt][1];
            float im1 = t3[mt][nt][1] - t1[mt][nt][1] - t2[mt][nt][1];
            float re2 = t1[mt][nt][2] - t2[mt][nt][2];
            float im2 = t3[mt][nt][2] - t1[mt][nt][2] - t2[mt][nt][2];
            float re3 = t1[mt][nt][3] - t2[mt][nt][3];
            float im3 = t3[mt][nt][3] - t1[mt][nt][3] - t2[mt][nt][3];
            *(float4*)(out + ((size_t)r_lo * HD + col) * 2) =
                make_float4(re0, im0, re1, im1);
            *(float4*)(out + ((size_t)(r_lo + 8) * HD + col) * 2) =
                make_float4(re2, im2, re3, im3);
        }
    }
}

extern "C" void kernel_launch(void* const* d_in, const int* in_sizes, int n_in,
                              void* d_out, int out_size) {
    const float* xre = (const float*)d_in[0];
    const float* xim = (const float*)d_in[1];
    const float* w   = (const float*)d_in[2];
    float* out       = (float*)d_out;

    cudaFuncSetAttribute(cbl_kar16_kernel,
                         cudaFuncAttributeMaxDynamicSharedMemorySize, SMEM_TOTAL);
    dim3 grid(32768 / CTA_M, NBLK);   // (512, 8)
    cbl_kar16_kernel<<<grid, THREADS, SMEM_TOTAL>>>(xre, xim, w, out);
}

// round 7
// speedup vs baseline: 1.2709x; 1.2709x over previous
#include <cuda_runtime.h>
#include <cstdint>

// ComplexBlockLinear, mma.sync tf32, Karatsuba 3-mult, cp.async double
// buffered, register-double-buffered fragments (software pipeline).
// CTA = 64 rows x 128 cols, 8 warps (2M x 4N), warp tile 32x32.
// t1=xr@wr, t2=xi@wi, t3=(xr+xi)@(wr+wi); re=t1-t2, im=t3-t1-t2.

#define NBLK 8
#define BS 128
#define HD 1024
#define CTA_M 64
#define KC 32
#define NCHUNK (BS / KC)     // 4
#define THREADS 256

// smem floats per stage: XR 64x36, XI 64x36, WW 32x264
#define XSTR 36
#define WSTR 264
#define XR_OFF 0
#define XI_OFF 9216
#define WW_OFF 18432
#define STAGE_BYTES (18432 + 33792)   // 52224
#define SMEM_TOTAL (2 * STAGE_BYTES)  // 104448

__device__ __forceinline__ unsigned f2tf(float x) {
    unsigned u;
    asm("cvt.rna.tf32.f32 %0, %1;" : "=r"(u) : "f"(x));
    return u;
}
__device__ __forceinline__ uint32_t smem_u32(const void* p) {
    uint32_t a;
    asm("{ .reg .u64 t; cvta.to.shared.u64 t, %1; cvt.u32.u64 %0, t; }"
        : "=r"(a) : "l"(p));
    return a;
}
__device__ __forceinline__ void cp16(uint32_t dst, const void* src) {
    asm volatile("cp.async.ca.shared.global [%0], [%1], 16;"
                 :: "r"(dst), "l"(src) : "memory");
}
__device__ __forceinline__ void cp_commit() {
    asm volatile("cp.async.commit_group;" ::: "memory");
}
template <int N>
__device__ __forceinline__ void cp_wait() {
    asm volatile("cp.async.wait_group %0;" :: "n"(N) : "memory");
}
__device__ __forceinline__ void mma_tf32(float* d, const unsigned* a,
                                         unsigned b0, unsigned b1) {
    asm volatile(
        "mma.sync.aligned.m16n8k8.row.col.f32.tf32.tf32.f32 "
        "{%0,%1,%2,%3},{%4,%5,%6,%7},{%8,%9},{%0,%1,%2,%3};\n"
        : "+f"(d[0]), "+f"(d[1]), "+f"(d[2]), "+f"(d[3])
        : "r"(a[0]), "r"(a[1]), "r"(a[2]), "r"(a[3]), "r"(b0), "r"(b1));
}

__global__ __launch_bounds__(THREADS)
void cbl_kpipe_kernel(const float* __restrict__ xre,
                      const float* __restrict__ xim,
                      const float* __restrict__ w,
                      float* __restrict__ out) {
    extern __shared__ char smem[];
    const uint32_t sb = smem_u32(smem);

    const int tid  = threadIdx.x;
    const int lane = tid & 31;
    const int warp = tid >> 5;
    const int wm   = warp >> 2;    // 0..1
    const int wn   = warp & 3;     // 0..3

    const int row0 = blockIdx.x * CTA_M;
    const int nb   = blockIdx.y;

    float t1[2][4][4], t2[2][4][4], t3[2][4][4];
#pragma unroll
    for (int a = 0; a < 2; a++)
#pragma unroll
        for (int b = 0; b < 4; b++)
#pragma unroll
            for (int c = 0; c < 4; c++) {
                t1[a][b][c] = 0.f; t2[a][b][c] = 0.f; t3[a][b][c] = 0.f;
            }

    // double-buffered fragments (buf dimension resolved at compile time)
    unsigned ar[2][2][4], ai[2][2][4], as_[2][2][4];   // [buf][mt][reg]
    unsigned bR[2][4][2], bI[2][4][2], bS[2][4][2];    // [buf][nt][half]

    auto issue = [&](int c) {
        const uint32_t base = sb + (c & 1) * STAGE_BYTES;
        const int k0 = c * KC;
        // X: 64 rows x 32 k x 2 arrays = 1024 16B-chunks, 4/thread
#pragma unroll
        for (int q = 0; q < 4; ++q) {
            const int e   = q * THREADS + tid;       // 0..1023
            const int arr = e >> 9;                  // 0: re, 1: im
            const int r   = (e >> 3) & 63;
            const int cc  = (e & 7) * 4;
            const float* src = (arr ? xim : xre) +
                (size_t)(row0 + r) * HD + nb * BS + k0 + cc;
            cp16(base + (arr ? XI_OFF : XR_OFF) + r * (XSTR * 4) + cc * 4, src);
        }
        // W: 32 k-rows x 64 chunks (16B = 2 complex) = 2048 chunks, 8/thread
#pragma unroll
        for (int q = 0; q < 8; ++q) {
            const int e  = q * THREADS + tid;        // 0..2047
            const int kk = e >> 6;                   // 0..31
            const int oc = e & 63;                   // 0..63
            const float* src = w +
                ((size_t)((nb * BS + k0 + kk) * BS) + oc * 2) * 2;
            cp16(base + WW_OFF + kk * (WSTR * 4) + oc * 16, src);
        }
        cp_commit();
    };

    issue(0);

#pragma unroll 1
    for (int c = 0; c < NCHUNK; ++c) {
        if (c + 1 < NCHUNK) { issue(c + 1); cp_wait<1>(); }
        else                { cp_wait<0>(); }
        __syncthreads();

        const float* sXR = (const float*)(smem + (c & 1) * STAGE_BYTES + XR_OFF);
        const float* sXI = (const float*)(smem + (c & 1) * STAGE_BYTES + XI_OFF);
        const float* sWW = (const float*)(smem + (c & 1) * STAGE_BYTES + WW_OFF);

        // fragment loader (buf must be a compile-time constant at each use)
        auto load_frag = [&](int buf, int ks) {
            const int kk = ks * 8;
#pragma unroll
            for (int mt = 0; mt < 2; ++mt) {
                const int rr = wm * 32 + mt * 16 + (lane >> 2);
                const int cc = kk + (lane & 3);
                const float fr0 = sXR[rr * XSTR + cc];
                const float fr1 = sXR[(rr + 8) * XSTR + cc];
                const float fr2 = sXR[rr * XSTR + cc + 4];
                const float fr3 = sXR[(rr + 8) * XSTR + cc + 4];
                const float fi0 = sXI[rr * XSTR + cc];
                const float fi1 = sXI[(rr + 8) * XSTR + cc];
                const float fi2 = sXI[rr * XSTR + cc + 4];
                const float fi3 = sXI[(rr + 8) * XSTR + cc + 4];
                ar[buf][mt][0] = f2tf(fr0); ar[buf][mt][1] = f2tf(fr1);
                ar[buf][mt][2] = f2tf(fr2); ar[buf][mt][3] = f2tf(fr3);
                ai[buf][mt][0] = f2tf(fi0); ai[buf][mt][1] = f2tf(fi1);
                ai[buf][mt][2] = f2tf(fi2); ai[buf][mt][3] = f2tf(fi3);
                as_[buf][mt][0] = f2tf(fr0 + fi0);
                as_[buf][mt][1] = f2tf(fr1 + fi1);
                as_[buf][mt][2] = f2tf(fr2 + fi2);
                as_[buf][mt][3] = f2tf(fr3 + fi3);
            }
#pragma unroll
            for (int nt = 0; nt < 4; ++nt) {
                const int n  = wn * 32 + nt * 8 + (lane >> 2);
                const int kb = kk + (lane & 3);
                const float2 p0 = *(const float2*)&sWW[kb * WSTR + n * 2];
                const float2 p1 = *(const float2*)&sWW[(kb + 4) * WSTR + n * 2];
                bR[buf][nt][0] = f2tf(p0.x);
                bI[buf][nt][0] = f2tf(p0.y);
                bS[buf][nt][0] = f2tf(p0.x + p0.y);
                bR[buf][nt][1] = f2tf(p1.x);
                bI[buf][nt][1] = f2tf(p1.y);
                bS[buf][nt][1] = f2tf(p1.x + p1.y);
            }
        };
        auto mma_all = [&](int buf) {
#pragma unroll
            for (int nt = 0; nt < 4; ++nt)
#pragma unroll
                for (int mt = 0; mt < 2; ++mt) {
                    mma_tf32(t1[mt][nt], ar[buf][mt],
                             bR[buf][nt][0], bR[buf][nt][1]);
                    mma_tf32(t2[mt][nt], ai[buf][mt],
                             bI[buf][nt][0], bI[buf][nt][1]);
                    mma_tf32(t3[mt][nt], as_[buf][mt],
                             bS[buf][nt][0], bS[buf][nt][1]);
                }
        };

        load_frag(0, 0);
#pragma unroll
        for (int ks = 0; ks < KC / 8; ++ks) {
            if (ks + 1 < KC / 8) load_frag((ks + 1) & 1, ks + 1);
            mma_all(ks & 1);
        }
        __syncthreads();
    }

    // epilogue: re = t1 - t2; im = t3 - t1 - t2; interleaved float4 stores
#pragma unroll
    for (int mt = 0; mt < 2; ++mt) {
        const int r_lo = row0 + wm * 32 + mt * 16 + (lane >> 2);
#pragma unroll
        for (int nt = 0; nt < 4; ++nt) {
            const int col = nb * BS + wn * 32 + nt * 8 + (lane & 3) * 2;
            float re0 = t1[mt][nt][0] - t2[mt][nt][0];
            float im0 = t3[mt][nt][0] - t1[mt][nt][0] - t2[mt][nt][0];
            float re1 = t1[mt][nt][1] - t2[mt][nt][1];
            float im1 = t3[mt][nt][1] - t1[mt][nt][1] - t2[mt][nt][1];
            float re2 = t1[mt][nt][2] - t2[mt][nt][2];
            float im2 = t3[mt][nt][2] - t1[mt][nt][2] - t2[mt][nt][2];
            float re3 = t1[mt][nt][3] - t2[mt][nt][3];
            float im3 = t3[mt][nt][3] - t1[mt][nt][3] - t2[mt][nt][3];
            *(float4*)(out + ((size_t)r_lo * HD + col) * 2) =
                make_float4(re0, im0, re1, im1);
            *(float4*)(out + ((size_t)(r_lo + 8) * HD + col) * 2) =
                make_float4(re2, im2, re3, im3);
        }
    }
}

extern "C" void kernel_launch(void* const* d_in, const int* in_sizes, int n_in,
                              void* d_out, int out_size) {
    const float* xre = (const float*)d_in[0];
    const float* xim = (const float*)d_in[1];
    const float* w   = (const float*)d_in[2];
    float* out       = (float*)d_out;

    cudaFuncSetAttribute(cbl_kpipe_kernel,
                         cudaFuncAttributeMaxDynamicSharedMemorySize, SMEM_TOTAL);
    dim3 grid(32768 / CTA_M, NBLK);   // (512, 8)
    cbl_kpipe_kernel<<<grid, THREADS, SMEM_TOTAL>>>(xre, xim, w, out);
}

// round 8
// speedup vs baseline: 1.5697x; 1.2351x over previous
#include <cuda_runtime.h>
#include <cstdint>

// ComplexBlockLinear, mma.sync fp16 m16n8k16 (same 10-bit mantissa as tf32),
// cp.async double-buffered. CTA = 128 rows x 1 block (128 cols), 16 warps
// (4M x 4N), warp tile 32x32, 4-mult complex. K chunked by 16.

#define NBLK 8
#define BS 128
#define HD 1024
#define CTA_M 128
#define KC 16
#define NCHUNK (BS / KC)     // 8
#define THREADS 512

// smem per stage:
//   XR/XI: 128 rows x 16 floats, XOR-group-swizzled (group^=(r&3))   8192 B each
//   WW:    16 k-rows x 260 floats (128 complex + 2 pad)             16640 B
#define WSTR 260
#define XR_OFF 0
#define XI_OFF 8192
#define WW_OFF 16384
#define STAGE_BYTES 33024
#define SMEM_TOTAL (2 * STAGE_BYTES)   // 66048

__device__ __forceinline__ uint32_t smem_u32(const void* p) {
    uint32_t a;
    asm("{ .reg .u64 t; cvta.to.shared.u64 t, %1; cvt.u32.u64 %0, t; }"
        : "=r"(a) : "l"(p));
    return a;
}
// pack two f32 -> f16x2, lo in low half (PTX: first src -> upper half)
__device__ __forceinline__ unsigned pack_h2(float lo, float hi) {
    unsigned d;
    asm("cvt.rn.f16x2.f32 %0, %1, %2;" : "=r"(d) : "f"(hi), "f"(lo));
    return d;
}
__device__ __forceinline__ void cp16(uint32_t dst, const void* src) {
    asm volatile("cp.async.ca.shared.global [%0], [%1], 16;"
                 :: "r"(dst), "l"(src) : "memory");
}
__device__ __forceinline__ void cp_commit() {
    asm volatile("cp.async.commit_group;" ::: "memory");
}
template <int N>
__device__ __forceinline__ void cp_wait() {
    asm volatile("cp.async.wait_group %0;" :: "n"(N) : "memory");
}
__device__ __forceinline__ void mma_f16(float* d, const unsigned* a,
                                        unsigned b0, unsigned b1) {
    asm volatile(
        "mma.sync.aligned.m16n8k16.row.col.f32.f16.f16.f32 "
        "{%0,%1,%2,%3},{%4,%5,%6,%7},{%8,%9},{%0,%1,%2,%3};\n"
        : "+f"(d[0]), "+f"(d[1]), "+f"(d[2]), "+f"(d[3])
        : "r"(a[0]), "r"(a[1]), "r"(a[2]), "r"(a[3]), "r"(b0), "r"(b1));
}

__global__ __launch_bounds__(THREADS)
void cbl_h16_kernel(const float* __restrict__ xre,
                    const float* __restrict__ xim,
                    const float* __restrict__ w,
                    float* __restrict__ out) {
    extern __shared__ char smem[];
    const uint32_t sb = smem_u32(smem);

    const int tid  = threadIdx.x;
    const int lane = tid & 31;
    const int warp = tid >> 5;
    const int wm   = warp >> 2;    // 0..3
    const int wn   = warp & 3;     // 0..3

    const int row0 = blockIdx.x * CTA_M;
    const int nb   = blockIdx.y;

    float accR[2][4][4], accI[2][4][4];
#pragma unroll
    for (int a = 0; a < 2; a++)
#pragma unroll
        for (int b = 0; b < 4; b++)
#pragma unroll
            for (int c = 0; c < 4; c++) { accR[a][b][c] = 0.f; accI[a][b][c] = 0.f; }

    auto issue = [&](int c) {
        const uint32_t base = sb + (c & 1) * STAGE_BYTES;
        const int k0 = c * KC;
        // X: 128 rows x 16 k x 2 arrays = 1024 16B chunks, 2/thread.
        // dst group swizzled: group' = t ^ (r&3)
#pragma unroll
        for (int q = 0; q < 2; ++q) {
            const int e   = q * THREADS + tid;     // 0..1023
            const int arr = e >> 9;                // 0: re, 1: im
            const int r   = (e >> 2) & 127;
            const int t   = e & 3;
            const float* src = (arr ? xim : xre) +
                (size_t)(row0 + r) * HD + nb * BS + k0 + t * 4;
            const uint32_t doff = (r * 16 + ((t ^ (r & 3)) * 4)) * 4;
            cp16(base + (arr ? XI_OFF : XR_OFF) + doff, src);
        }
        // W: 16 k-rows x 64 chunks (16B = 2 complex) = 1024 chunks, 2/thread
#pragma unroll
        for (int q = 0; q < 2; ++q) {
            const int e  = q * THREADS + tid;
            const int kk = e >> 6;                 // 0..15
            const int oc = e & 63;                 // 0..63
            const float* src = w +
                ((size_t)((nb * BS + k0 + kk) * BS) + oc * 2) * 2;
            cp16(base + WW_OFF + (kk * WSTR + oc * 4) * 4, src);
        }
        cp_commit();
    };

    issue(0);

#pragma unroll 1
    for (int c = 0; c < NCHUNK; ++c) {
        if (c + 1 < NCHUNK) { issue(c + 1); cp_wait<1>(); }
        else                { cp_wait<0>(); }
        __syncthreads();

        const float* sXR = (const float*)(smem + (c & 1) * STAGE_BYTES + XR_OFF);
        const float* sXI = (const float*)(smem + (c & 1) * STAGE_BYTES + XI_OFF);
        const float* sWW = (const float*)(smem + (c & 1) * STAGE_BYTES + WW_OFF);

        // ---- A fragments (full k=16 chunk), xr & xi, f16x2-packed
        unsigned ar[2][4], ai[2][4];
        const int g = lane >> 2;
        const int t = lane & 3;
#pragma unroll
        for (int mt = 0; mt < 2; ++mt) {
            const int rr = wm * 32 + mt * 16 + g;     // rr and rr+8: same (r&3)
            const int s  = rr & 3;
            const int c_lo = (((t >> 1) ^ s) << 2) + (2 * t & 2);       // k=2t,2t+1
            const int c_hi = ((((t >> 1) + 2) ^ s) << 2) + (2 * t & 2); // k+8
            float2 v;
            v = *(const float2*)&sXR[rr * 16 + c_lo];
            ar[mt][0] = pack_h2(v.x, v.y);
            v = *(const float2*)&sXR[(rr + 8) * 16 + c_lo];
            ar[mt][1] = pack_h2(v.x, v.y);
            v = *(const float2*)&sXR[rr * 16 + c_hi];
            ar[mt][2] = pack_h2(v.x, v.y);
            v = *(const float2*)&sXR[(rr + 8) * 16 + c_hi];
            ar[mt][3] = pack_h2(v.x, v.y);
            v = *(const float2*)&sXI[rr * 16 + c_lo];
            ai[mt][0] = pack_h2(v.x, v.y);
            v = *(const float2*)&sXI[(rr + 8) * 16 + c_lo];
            ai[mt][1] = pack_h2(v.x, v.y);
            v = *(const float2*)&sXI[rr * 16 + c_hi];
            ai[mt][2] = pack_h2(v.x, v.y);
            v = *(const float2*)&sXI[(rr + 8) * 16 + c_hi];
            ai[mt][3] = pack_h2(v.x, v.y);
        }

        // ---- B fragments + mma per n-tile
#pragma unroll
        for (int nt = 0; nt < 4; ++nt) {
            const int n = wn * 32 + nt * 8 + g;
            const float* col = sWW + n * 2;
            const float2 kA = *(const float2*)&col[(2 * t) * WSTR];
            const float2 kB = *(const float2*)&col[(2 * t + 1) * WSTR];
            const float2 kC = *(const float2*)&col[(2 * t + 8) * WSTR];
            const float2 kD = *(const float2*)&col[(2 * t + 9) * WSTR];
            const unsigned bR0 = pack_h2(kA.x, kB.x);
            const unsigned bI0 = pack_h2(kA.y, kB.y);
            const unsigned bR1 = pack_h2(kC.x, kD.x);
            const unsigned bI1 = pack_h2(kC.y, kD.y);
            const unsigned nI0 = bI0 ^ 0x80008000u;
            const unsigned nI1 = bI1 ^ 0x80008000u;
#pragma unroll
            for (int mt = 0; mt < 2; ++mt) {
                mma_f16(accR[mt][nt], ar[mt], bR0, bR1);
                mma_f16(accR[mt][nt], ai[mt], nI0, nI1);
                mma_f16(accI[mt][nt], ar[mt], bI0, bI1);
                mma_f16(accI[mt][nt], ai[mt], bR0, bR1);
            }
        }
        __syncthreads();   // buffer free for stage c+2
    }

    // ---- epilogue: interleave (re,im) -> float4 stores, view_as_real layout
#pragma unroll
    for (int mt = 0; mt < 2; ++mt) {
        const int r_lo = row0 + wm * 32 + mt * 16 + (lane >> 2);
#pragma unroll
        for (int nt = 0; nt < 4; ++nt) {
            const int col = nb * BS + wn * 32 + nt * 8 + (lane & 3) * 2;
            float4 v0 = make_float4(accR[mt][nt][0], accI[mt][nt][0],
                                    accR[mt][nt][1], accI[mt][nt][1]);
            float4 v1 = make_float4(accR[mt][nt][2], accI[mt][nt][2],
                                    accR[mt][nt][3], accI[mt][nt][3]);
            *(float4*)(out + ((size_t)r_lo * HD + col) * 2)       = v0;
            *(float4*)(out + ((size_t)(r_lo + 8) * HD + col) * 2) = v1;
        }
    }
}

extern "C" void kernel_launch(void* const* d_in, const int* in_sizes, int n_in,
                              void* d_out, int out_size) {
    const float* xre = (const float*)d_in[0];
    const float* xim = (const float*)d_in[1];
    const float* w   = (const float*)d_in[2];
    float* out       = (float*)d_out;

    cudaFuncSetAttribute(cbl_h16_kernel,
                         cudaFuncAttributeMaxDynamicSharedMemorySize, SMEM_TOTAL);
    dim3 grid(32768 / CTA_M, NBLK);   // (256, 8)
    cbl_h16_kernel<<<grid, THREADS, SMEM_TOTAL>>>(xre, xim, w, out);
}

// round 9
// speedup vs baseline: 1.8210x; 1.1601x over previous
#include <cuda_runtime.h>
#include <cstdint>

// ComplexBlockLinear, mma.sync fp16 m16n8k16, cp.async double-buffered.
// CTA = 64 rows x 1 block (128 cols), 8 warps (2M x 4N), warp tile 32x32.
// 256 thr, <=128 regs -> 2 CTAs/SM. KC=32 (4 chunks, fewer syncs).

#define NBLK 8
#define BS 128
#define HD 1024
#define CTA_M 64
#define KC 32
#define NCHUNK (BS / KC)     // 4
#define THREADS 256

// smem per stage:
//   XR/XI: 2 k16-halves x 64 rows x 16 floats, XOR-group swizzle   8192 B each
//   WW:    32 k-rows x 260 floats                                 33280 B
#define WSTR 260
#define XR_OFF 0
#define XI_OFF 8192
#define WW_OFF 16384
#define STAGE_BYTES (16384 + 33280)    // 49664
#define SMEM_TOTAL (2 * STAGE_BYTES)   // 99328

__device__ __forceinline__ uint32_t smem_u32(const void* p) {
    uint32_t a;
    asm("{ .reg .u64 t; cvta.to.shared.u64 t, %1; cvt.u32.u64 %0, t; }"
        : "=r"(a) : "l"(p));
    return a;
}
// pack two f32 -> f16x2, lo in low half
__device__ __forceinline__ unsigned pack_h2(float lo, float hi) {
    unsigned d;
    asm("cvt.rn.f16x2.f32 %0, %1, %2;" : "=r"(d) : "f"(hi), "f"(lo));
    return d;
}
__device__ __forceinline__ void cp16(uint32_t dst, const void* src) {
    asm volatile("cp.async.ca.shared.global [%0], [%1], 16;"
                 :: "r"(dst), "l"(src) : "memory");
}
__device__ __forceinline__ void cp_commit() {
    asm volatile("cp.async.commit_group;" ::: "memory");
}
template <int N>
__device__ __forceinline__ void cp_wait() {
    asm volatile("cp.async.wait_group %0;" :: "n"(N) : "memory");
}
__device__ __forceinline__ void mma_f16(float* d, const unsigned* a,
                                        unsigned b0, unsigned b1) {
    asm volatile(
        "mma.sync.aligned.m16n8k16.row.col.f32.f16.f16.f32 "
        "{%0,%1,%2,%3},{%4,%5,%6,%7},{%8,%9},{%0,%1,%2,%3};\n"
        : "+f"(d[0]), "+f"(d[1]), "+f"(d[2]), "+f"(d[3])
        : "r"(a[0]), "r"(a[1]), "r"(a[2]), "r"(a[3]), "r"(b0), "r"(b1));
}

__global__ __launch_bounds__(THREADS, 2)
void cbl_h16o_kernel(const float* __restrict__ xre,
                     const float* __restrict__ xim,
                     const float* __restrict__ w,
                     float* __restrict__ out) {
    extern __shared__ char smem[];
    const uint32_t sb = smem_u32(smem);

    const int tid  = threadIdx.x;
    const int lane = tid & 31;
    const int warp = tid >> 5;
    const int wm   = warp >> 2;    // 0..1
    const int wn   = warp & 3;     // 0..3

    const int row0 = blockIdx.x * CTA_M;
    const int nb   = blockIdx.y;

    float accR[2][4][4], accI[2][4][4];
#pragma unroll
    for (int a = 0; a < 2; a++)
#pragma unroll
        for (int b = 0; b < 4; b++)
#pragma unroll
            for (int c = 0; c < 4; c++) { accR[a][b][c] = 0.f; accI[a][b][c] = 0.f; }

    auto issue = [&](int c) {
        const uint32_t base = sb + (c & 1) * STAGE_BYTES;
        const int k0 = c * KC;
        // X: 2 arrays x 2 halves x 64 rows x 4 groups = 1024 chunks, 4/thread
#pragma unroll
        for (int q = 0; q < 4; ++q) {
            const int e   = q * THREADS + tid;     // 0..1023
            const int arr = e >> 9;                // 0: re, 1: im
            const int s   = (e >> 8) & 1;          // k16 half
            const int r   = (e >> 2) & 63;
            const int t   = e & 3;
            const float* src = (arr ? xim : xre) +
                (size_t)(row0 + r) * HD + nb * BS + k0 + s * 16 + t * 4;
            const uint32_t doff = ((s * 64 + r) * 16 + ((t ^ (r & 3)) * 4)) * 4;
            cp16(base + (arr ? XI_OFF : XR_OFF) + doff, src);
        }
        // W: 32 k-rows x 64 chunks (16B = 2 complex) = 2048 chunks, 8/thread
#pragma unroll
        for (int q = 0; q < 8; ++q) {
            const int e  = q * THREADS + tid;
            const int kk = e >> 6;                 // 0..31
            const int oc = e & 63;                 // 0..63
            const float* src = w +
                ((size_t)((nb * BS + k0 + kk) * BS) + oc * 2) * 2;
            cp16(base + WW_OFF + (kk * WSTR + oc * 4) * 4, src);
        }
        cp_commit();
    };

    issue(0);

#pragma unroll 1
    for (int c = 0; c < NCHUNK; ++c) {
        if (c + 1 < NCHUNK) { issue(c + 1); cp_wait<1>(); }
        else                { cp_wait<0>(); }
        __syncthreads();

        const float* sXR = (const float*)(smem + (c & 1) * STAGE_BYTES + XR_OFF);
        const float* sXI = (const float*)(smem + (c & 1) * STAGE_BYTES + XI_OFF);
        const float* sWW = (const float*)(smem + (c & 1) * STAGE_BYTES + WW_OFF);

        const int g = lane >> 2;
        const int t = lane & 3;

#pragma unroll
        for (int s = 0; s < 2; ++s) {     // two k16 steps per chunk
            // ---- A fragments, xr & xi, f16x2-packed
            unsigned ar[2][4], ai[2][4];
#pragma unroll
            for (int mt = 0; mt < 2; ++mt) {
                const int rr = s * 64 + wm * 32 + mt * 16 + g;
                const int sz = rr & 3;
                const int c_lo = (((t >> 1) ^ sz) << 2) + (2 * t & 2);
                const int c_hi = ((((t >> 1) + 2) ^ sz) << 2) + (2 * t & 2);
                float2 v;
                v = *(const float2*)&sXR[rr * 16 + c_lo];
                ar[mt][0] = pack_h2(v.x, v.y);
                v = *(const float2*)&sXR[(rr + 8) * 16 + c_lo];
                ar[mt][1] = pack_h2(v.x, v.y);
                v = *(const float2*)&sXR[rr * 16 + c_hi];
                ar[mt][2] = pack_h2(v.x, v.y);
                v = *(const float2*)&sXR[(rr + 8) * 16 + c_hi];
                ar[mt][3] = pack_h2(v.x, v.y);
                v = *(const float2*)&sXI[rr * 16 + c_lo];
                ai[mt][0] = pack_h2(v.x, v.y);
                v = *(const float2*)&sXI[(rr + 8) * 16 + c_lo];
                ai[mt][1] = pack_h2(v.x, v.y);
                v = *(const float2*)&sXI[rr * 16 + c_hi];
                ai[mt][2] = pack_h2(v.x, v.y);
                v = *(const float2*)&sXI[(rr + 8) * 16 + c_hi];
                ai[mt][3] = pack_h2(v.x, v.y);
            }

            // ---- B fragments + mma per n-tile
#pragma unroll
            for (int nt = 0; nt < 4; ++nt) {
                const int n = wn * 32 + nt * 8 + g;
                const float* col = sWW + n * 2;
                const float2 kA = *(const float2*)&col[(s * 16 + 2 * t) * WSTR];
                const float2 kB = *(const float2*)&col[(s * 16 + 2 * t + 1) * WSTR];
                const float2 kC = *(const float2*)&col[(s * 16 + 2 * t + 8) * WSTR];
                const float2 kD = *(const float2*)&col[(s * 16 + 2 * t + 9) * WSTR];
                const unsigned bR0 = pack_h2(kA.x, kB.x);
                const unsigned bI0 = pack_h2(kA.y, kB.y);
                const unsigned bR1 = pack_h2(kC.x, kD.x);
                const unsigned bI1 = pack_h2(kC.y, kD.y);
                const unsigned nI0 = bI0 ^ 0x80008000u;
                const unsigned nI1 = bI1 ^ 0x80008000u;
#pragma unroll
                for (int mt = 0; mt < 2; ++mt) {
                    mma_f16(accR[mt][nt], ar[mt], bR0, bR1);
                    mma_f16(accR[mt][nt], ai[mt], nI0, nI1);
                    mma_f16(accI[mt][nt], ar[mt], bI0, bI1);
                    mma_f16(accI[mt][nt], ai[mt], bR0, bR1);
                }
            }
        }
        __syncthreads();   // buffer free for stage c+2
    }

    // ---- epilogue: interleave (re,im) -> float4 stores, view_as_real layout
#pragma unroll
    for (int mt = 0; mt < 2; ++mt) {
        const int r_lo = row0 + wm * 32 + mt * 16 + (lane >> 2);
#pragma unroll
        for (int nt = 0; nt < 4; ++nt) {
            const int col = nb * BS + wn * 32 + nt * 8 + (lane & 3) * 2;
            float4 v0 = make_float4(accR[mt][nt][0], accI[mt][nt][0],
                                    accR[mt][nt][1], accI[mt][nt][1]);
            float4 v1 = make_float4(accR[mt][nt][2], accI[mt][nt][2],
                                    accR[mt][nt][3], accI[mt][nt][3]);
            *(float4*)(out + ((size_t)r_lo * HD + col) * 2)       = v0;
            *(float4*)(out + ((size_t)(r_lo + 8) * HD + col) * 2) = v1;
        }
    }
}

extern "C" void kernel_launch(void* const* d_in, const int* in_sizes, int n_in,
                              void* d_out, int out_size) {
    const float* xre = (const float*)d_in[0];
    const float* xim = (const float*)d_in[1];
    const float* w   = (const float*)d_in[2];
    float* out       = (float*)d_out;

    cudaFuncSetAttribute(cbl_h16o_kernel,
                         cudaFuncAttributeMaxDynamicSharedMemorySize, SMEM_TOTAL);
    dim3 grid(32768 / CTA_M, NBLK);   // (512, 8)
    cbl_h16o_kernel<<<grid, THREADS, SMEM_TOTAL>>>(xre, xim, w, out);
}

// round 10
// speedup vs baseline: 2.2120x; 1.2147x over previous
#include <cuda_runtime.h>
#include <cuda_fp16.h>
#include <cstdint>

// ComplexBlockLinear, mma.sync fp16 m16n8k16.
// Weight pre-converted to planar f16 (g_wre/g_wim) by a helper kernel once
// per launch; main kernel cp.asyncs W as f16 and loads B fragments via
// ldmatrix.x2.trans. X path identical to round 9 (cp.async f32 + pack).
// CTA = 64 rows x 1 block, 8 warps (2M x 4N), warp tile 32x32, KC=32,
// 256 thr, 2 CTAs/SM.

#define NBLK 8
#define BS 128
#define HD 1024
#define CTA_M 64
#define KC 32
#define NCHUNK (BS / KC)     // 4
#define THREADS 256

// smem per stage:
//   XR/XI: 2 k16-halves x 64 rows x 16 f32, XOR-group swizzle   8192 B each
//   WR/WI: 32 k-rows x 272 B (128 f16 + 8 pad)                  8704 B each
#define XR_OFF 0
#define XI_OFF 8192
#define WR_OFF 16384
#define WI_OFF 25088
#define STAGE_BYTES 33792
#define SMEM_TOTAL (2 * STAGE_BYTES)   // 67584
#define WROWB 272

// pre-converted weight planes, [nblk*128 k][128 n] f16
__device__ __align__(16) __half g_wre[NBLK * BS * BS];
__device__ __align__(16) __half g_wim[NBLK * BS * BS];

__device__ __forceinline__ uint32_t smem_u32(const void* p) {
    uint32_t a;
    asm("{ .reg .u64 t; cvta.to.shared.u64 t, %1; cvt.u32.u64 %0, t; }"
        : "=r"(a) : "l"(p));
    return a;
}
// pack two f32 -> f16x2, lo in low half
__device__ __forceinline__ unsigned pack_h2(float lo, float hi) {
    unsigned d;
    asm("cvt.rn.f16x2.f32 %0, %1, %2;" : "=r"(d) : "f"(hi), "f"(lo));
    return d;
}
__device__ __forceinline__ void cp16(uint32_t dst, const void* src) {
    asm volatile("cp.async.ca.shared.global [%0], [%1], 16;"
                 :: "r"(dst), "l"(src) : "memory");
}
__device__ __forceinline__ void cp_commit() {
    asm volatile("cp.async.commit_group;" ::: "memory");
}
template <int N>
__device__ __forceinline__ void cp_wait() {
    asm volatile("cp.async.wait_group %0;" :: "n"(N) : "memory");
}
__device__ __forceinline__ void ldsm_x2t(unsigned& r0, unsigned& r1,
                                         uint32_t addr) {
    asm volatile("ldmatrix.sync.aligned.m8n8.x2.trans.shared.b16 {%0,%1},[%2];"
                 : "=r"(r0), "=r"(r1) : "r"(addr));
}
__device__ __forceinline__ void mma_f16(float* d, const unsigned* a,
                                        unsigned b0, unsigned b1) {
    asm volatile(
        "mma.sync.aligned.m16n8k16.row.col.f32.f16.f16.f32 "
        "{%0,%1,%2,%3},{%4,%5,%6,%7},{%8,%9},{%0,%1,%2,%3};\n"
        : "+f"(d[0]), "+f"(d[1]), "+f"(d[2]), "+f"(d[3])
        : "r"(a[0]), "r"(a[1]), "r"(a[2]), "r"(a[3]), "r"(b0), "r"(b1));
}

// ---- weight conversion: [8,128,128,2] f32 -> planar f16 ----
__global__ void wconv_kernel(const float* __restrict__ w) {
    const int idx = blockIdx.x * 256 + threadIdx.x;   // 0..131071
    const float2 v = ((const float2*)w)[idx];
    g_wre[idx] = __float2half_rn(v.x);
    g_wim[idx] = __float2half_rn(v.y);
}

__global__ __launch_bounds__(THREADS, 2)
void cbl_h16w_kernel(const float* __restrict__ xre,
                     const float* __restrict__ xim,
                     float* __restrict__ out) {
    extern __shared__ char smem[];
    const uint32_t sb = smem_u32(smem);

    const int tid  = threadIdx.x;
    const int lane = tid & 31;
    const int warp = tid >> 5;
    const int wm   = warp >> 2;    // 0..1
    const int wn   = warp & 3;     // 0..3

    const int row0 = blockIdx.x * CTA_M;
    const int nb   = blockIdx.y;

    float accR[2][4][4], accI[2][4][4];
#pragma unroll
    for (int a = 0; a < 2; a++)
#pragma unroll
        for (int b = 0; b < 4; b++)
#pragma unroll
            for (int c = 0; c < 4; c++) { accR[a][b][c] = 0.f; accI[a][b][c] = 0.f; }

    auto issue = [&](int c) {
        const uint32_t base = sb + (c & 1) * STAGE_BYTES;
        const int k0 = c * KC;
        // X: 2 arrays x 2 halves x 64 rows x 4 groups = 1024 chunks, 4/thread
#pragma unroll
        for (int q = 0; q < 4; ++q) {
            const int e   = q * THREADS + tid;     // 0..1023
            const int arr = e >> 9;                // 0: re, 1: im
            const int s   = (e >> 8) & 1;          // k16 half
            const int r   = (e >> 2) & 63;
            const int t   = e & 3;
            const float* src = (arr ? xim : xre) +
                (size_t)(row0 + r) * HD + nb * BS + k0 + s * 16 + t * 4;
            const uint32_t doff = ((s * 64 + r) * 16 + ((t ^ (r & 3)) * 4)) * 4;
            cp16(base + (arr ? XI_OFF : XR_OFF) + doff, src);
        }
        // W f16: 2 arrays x 32 k-rows x 16 chunks (16B = 8 f16) = 1024, 4/thread
#pragma unroll
        for (int q = 0; q < 4; ++q) {
            const int e   = q * THREADS + tid;     // 0..1023
            const int arr = e >> 9;
            const int kk  = (e >> 4) & 31;
            const int c16 = e & 15;
            const __half* src = (arr ? g_wim : g_wre) +
                (size_t)(nb * BS + k0 + kk) * BS + c16 * 8;
            cp16(base + (arr ? WI_OFF : WR_OFF) + kk * WROWB + c16 * 16, src);
        }
        cp_commit();
    };

    issue(0);

    // B ldmatrix lane-invariant k offset
    const int kr_l = (lane & 7) + ((lane >> 3) & 1) * 8;

#pragma unroll 1
    for (int c = 0; c < NCHUNK; ++c) {
        if (c + 1 < NCHUNK) { issue(c + 1); cp_wait<1>(); }
        else                { cp_wait<0>(); }
        __syncthreads();

        const uint32_t base = sb + (c & 1) * STAGE_BYTES;
        const float* sXR = (const float*)(smem + (c & 1) * STAGE_BYTES + XR_OFF);
        const float* sXI = (const float*)(smem + (c & 1) * STAGE_BYTES + XI_OFF);

        const int g = lane >> 2;
        const int t = lane & 3;

#pragma unroll
        for (int s = 0; s < 2; ++s) {     // two k16 steps per chunk
            // ---- A fragments from f32 X smem (round-9 path)
            unsigned ar[2][4], ai[2][4];
#pragma unroll
            for (int mt = 0; mt < 2; ++mt) {
                const int rr = s * 64 + wm * 32 + mt * 16 + g;
                const int sz = rr & 3;
                const int c_lo = (((t >> 1) ^ sz) << 2) + (2 * t & 2);
                const int c_hi = ((((t >> 1) + 2) ^ sz) << 2) + (2 * t & 2);
                float2 v;
                v = *(const float2*)&sXR[rr * 16 + c_lo];
                ar[mt][0] = pack_h2(v.x, v.y);
                v = *(const float2*)&sXR[(rr + 8) * 16 + c_lo];
                ar[mt][1] = pack_h2(v.x, v.y);
                v = *(const float2*)&sXR[rr * 16 + c_hi];
                ar[mt][2] = pack_h2(v.x, v.y);
                v = *(const float2*)&sXR[(rr + 8) * 16 + c_hi];
                ar[mt][3] = pack_h2(v.x, v.y);
                v = *(const float2*)&sXI[rr * 16 + c_lo];
                ai[mt][0] = pack_h2(v.x, v.y);
                v = *(const float2*)&sXI[(rr + 8) * 16 + c_lo];
                ai[mt][1] = pack_h2(v.x, v.y);
                v = *(const float2*)&sXI[rr * 16 + c_hi];
                ai[mt][2] = pack_h2(v.x, v.y);
                v = *(const float2*)&sXI[(rr + 8) * 16 + c_hi];
                ai[mt][3] = pack_h2(v.x, v.y);
            }

            // ---- B fragments via ldmatrix.x2.trans from f16 W smem
            const uint32_t krow = (uint32_t)(s * 16 + kr_l) * WROWB;
#pragma unroll
            for (int nt = 0; nt < 4; ++nt) {
                const uint32_t ncol = (uint32_t)(wn * 32 + nt * 8) * 2;
                unsigned bR0, bR1, bI0, bI1;
                ldsm_x2t(bR0, bR1, base + WR_OFF + krow + ncol);
                ldsm_x2t(bI0, bI1, base + WI_OFF + krow + ncol);
                const unsigned nI0 = bI0 ^ 0x80008000u;
                const unsigned nI1 = bI1 ^ 0x80008000u;
#pragma unroll
                for (int mt = 0; mt < 2; ++mt) {
                    mma_f16(accR[mt][nt], ar[mt], bR0, bR1);
                    mma_f16(accR[mt][nt], ai[mt], nI0, nI1);
                    mma_f16(accI[mt][nt], ar[mt], bI0, bI1);
                    mma_f16(accI[mt][nt], ai[mt], bR0, bR1);
                }
            }
        }
        __syncthreads();   // buffer free for stage c+2
    }

    // ---- epilogue: interleave (re,im) -> float4 stores, view_as_real layout
#pragma unroll
    for (int mt = 0; mt < 2; ++mt) {
        const int r_lo = row0 + wm * 32 + mt * 16 + (lane >> 2);
#pragma unroll
        for (int nt = 0; nt < 4; ++nt) {
            const int col = nb * BS + wn * 32 + nt * 8 + (lane & 3) * 2;
            float4 v0 = make_float4(accR[mt][nt][0], accI[mt][nt][0],
                                    accR[mt][nt][1], accI[mt][nt][1]);
            float4 v1 = make_float4(accR[mt][nt][2], accI[mt][nt][2],
                                    accR[mt][nt][3], accI[mt][nt][3]);
            *(float4*)(out + ((size_t)r_lo * HD + col) * 2)       = v0;
            *(float4*)(out + ((size_t)(r_lo + 8) * HD + col) * 2) = v1;
        }
    }
}

extern "C" void kernel_launch(void* const* d_in, const int* in_sizes, int n_in,
                              void* d_out, int out_size) {
    const float* xre = (const float*)d_in[0];
    const float* xim = (const float*)d_in[1];
    const float* w   = (const float*)d_in[2];
    float* out       = (float*)d_out;

    wconv_kernel<<<NBLK * BS * BS / 256, 256>>>(w);

    cudaFuncSetAttribute(cbl_h16w_kernel,
                         cudaFuncAttributeMaxDynamicSharedMemorySize, SMEM_TOTAL);
    dim3 grid(32768 / CTA_M, NBLK);   // (512, 8)
    cbl_h16w_kernel<<<grid, THREADS, SMEM_TOTAL>>>(xre, xim, out);
}